// round 9
// baseline (speedup 1.0000x reference)
#include <cuda_runtime.h>

// QAttentionLayer: out[..., i] = cumprod_{j<=i}( cos(x_j) * cos(w_j) )
// x: [16384, 256, 10] fp32. 256-bit (v8) loads/stores: lcm(10,8)=40 ->
// 5-lane groups of 40 floats (4 rows), each lane owns ONE 32B chunk.
// Cross-lane prefix needs only ONE SHFL.IDX (lane k reads lane k-1's
// suffix product since its last row reset). Loads branchless (idle/tail
// lanes clamp onto a sector an active lane already fetches); stores
// predicated. ILP=4 front-batched LDG.256 = 128B/thread in flight.

#define NQ  10
#define ILP 4

__device__ __forceinline__ void ldg256(const float* p, float* v)
{
    unsigned r0, r1, r2, r3, r4, r5, r6, r7;
    asm("ld.global.nc.v8.b32 {%0,%1,%2,%3,%4,%5,%6,%7}, [%8];"
        : "=r"(r0), "=r"(r1), "=r"(r2), "=r"(r3),
          "=r"(r4), "=r"(r5), "=r"(r6), "=r"(r7)
        : "l"(p));
    v[0] = __uint_as_float(r0); v[1] = __uint_as_float(r1);
    v[2] = __uint_as_float(r2); v[3] = __uint_as_float(r3);
    v[4] = __uint_as_float(r4); v[5] = __uint_as_float(r5);
    v[6] = __uint_as_float(r6); v[7] = __uint_as_float(r7);
}

__device__ __forceinline__ void stg256(float* p, const float* v)
{
    asm volatile("st.global.cs.v8.b32 [%0], {%1,%2,%3,%4,%5,%6,%7,%8};"
        :: "l"(p),
           "r"(__float_as_uint(v[0])), "r"(__float_as_uint(v[1])),
           "r"(__float_as_uint(v[2])), "r"(__float_as_uint(v[3])),
           "r"(__float_as_uint(v[4])), "r"(__float_as_uint(v[5])),
           "r"(__float_as_uint(v[6])), "r"(__float_as_uint(v[7]))
        : "memory");
}

__global__ __launch_bounds__(256, 4)
void qattn_main(const float* __restrict__ x,
                float* __restrict__ o,
                const float* __restrict__ w,
                int n_groups)
{
    int tid  = blockIdx.x * blockDim.x + threadIdx.x;
    int warp = tid >> 5;
    int lane = tid & 31;
    int gw   = lane / 5;          // group slot within warp tile: 0..6 (6 => idle)
    int k    = lane - gw * 5;     // 32B chunk within 40-float group: 0..4
    int base = lane - k;          // first lane of this 5-lane group
    bool lane_ok = (gw < 6);

    // Weight cosines for positions p = 8k..8k+7 (q = p mod 10), computed once.
    float cw[8];
#pragma unroll
    for (int j = 0; j < 8; j++) {
        int q = 8 * k + j;
        q = (q >= 30) ? q - 30 : (q >= 20) ? q - 20 : (q >= 10) ? q - 10 : q;
        cw[j] = __cosf(__ldg(&w[q]));
    }

    // Row resets within this lane's 8 elements: k=1 -> j=2, k=2 -> j=4, k=3 -> j=6.
    bool b2 = (k == 1), b4 = (k == 2), b6 = (k == 3);
    int srcPrev = base + ((k == 0) ? 0 : k - 1);

    int g0 = warp * (6 * ILP) + gw;   // first 40-float group of this lane
    int gsub = lane_ok ? 0 : 6;       // idle lanes alias an active lane's sector

    float a[ILP][8];
    // Front-batch ALL loads, branchless (clamped addresses). MLP = ILP.
#pragma unroll
    for (int it = 0; it < ILP; it++) {
        int g = g0 + it * 6 - gsub;
        g = (g < n_groups) ? g : n_groups - 1;
        ldg256(&x[(long long)g * 40 + k * 8], a[it]);
    }

#pragma unroll
    for (int it = 0; it < ILP; it++) {
        float c0 = __cosf(a[it][0]) * cw[0];
        float c1 = __cosf(a[it][1]) * cw[1];
        float c2 = __cosf(a[it][2]) * cw[2];
        float c3 = __cosf(a[it][3]) * cw[3];
        float c4 = __cosf(a[it][4]) * cw[4];
        float c5 = __cosf(a[it][5]) * cw[5];
        float c6 = __cosf(a[it][6]) * cw[6];
        float c7 = __cosf(a[it][7]) * cw[7];

        // Local segmented inclusive scan (resets at b2/b4/b6 positions)
        float lp0 = c0;
        float lp1 = lp0 * c1;
        float lp2 = b2 ? c2 : lp1 * c2;
        float lp3 = lp2 * c3;
        float lp4 = b4 ? c4 : lp3 * c4;
        float lp5 = lp4 * c5;
        float lp6 = b6 ? c6 : lp5 * c6;
        float lp7 = lp6 * c7;

        // lp7 = product since this lane's last row start -> lane k+1's prefix.
        float s = __shfl_sync(0xffffffffu, lp7, srcPrev);
        float pre  = (k == 0) ? 1.0f : s;
        float preB = b2 ? 1.0f : pre;
        float preC = (b2 | b4) ? 1.0f : pre;
        float preD = (b2 | b4 | b6) ? 1.0f : pre;

        float r[8];
        r[0] = lp0 * pre;  r[1] = lp1 * pre;
        r[2] = lp2 * preB; r[3] = lp3 * preB;
        r[4] = lp4 * preC; r[5] = lp5 * preC;
        r[6] = lp6 * preD; r[7] = lp7 * preD;

        int g = g0 + it * 6;
        if (lane_ok && g < n_groups)
            stg256(&o[(long long)g * 40 + k * 8], r);
    }
}

extern "C" void kernel_launch(void* const* d_in, const int* in_sizes, int n_in,
                              void* d_out, int out_size)
{
    const float* x = (const float*)d_in[0];   // [16384*256*10] fp32
    const float* w = (const float*)d_in[1];   // [10] fp32
    float* out = (float*)d_out;

    long long total = (long long)in_sizes[0];   // 41,943,040 floats
    int n_groups    = (int)(total / 40);        // 1,048,576 groups of 40 floats
    long long warps = ((long long)n_groups + 6 * ILP - 1) / (6 * ILP);
    long long threads = warps * 32;
    int block = 256;
    long long grid = (threads + block - 1) / block;

    qattn_main<<<(unsigned)grid, block>>>(x, out, w, n_groups);
}

// round 10
// speedup vs baseline: 1.0304x; 1.0304x over previous
#include <cuda_runtime.h>

// QAttentionLayer: out[..., i] = cumprod_{j<=i}( cos(x_j) * cos(w_j) )
// x: [16384, 256, 10] fp32. Rows of 10 floats; lcm(10,4)=20 -> 5-lane groups,
// each lane owns ONE contiguous float4 (perfect coalescing), cross-lane prefix
// product via 2 SHFL.IDX. ILP=8: 8 front-batched LDG.128 per thread (MLP_p1=8).
// Single uniform predicated path. launch_bounds(256,5) -> 48 regs, 5 CTAs/SM.
//
// CONVERGED (R8 best): 335.5MB @ 46.2us = 7.26 TB/s (~91% of HBM spec, at the
// B300 LTS path-independent cap). Measured losers: control-flow specialization
// (R5), persistent double-buffer pipeline (R7), 256-bit v8 memory ops (R9).

#define NQ  10
#define ILP 8

__global__ __launch_bounds__(256, 5)
void qattn_main(const float4* __restrict__ x4,
                float4* __restrict__ o4,
                const float* __restrict__ w,
                int n_groups)
{
    int tid  = blockIdx.x * blockDim.x + threadIdx.x;
    int warp = tid >> 5;
    int lane = tid & 31;
    int gw   = lane / 5;          // group slot within warp tile: 0..6 (6 => idle)
    int k    = lane - gw * 5;     // float4 slot within group: 0..4
    int base = lane - k;          // first lane of this 5-lane group
    bool lane_ok = (gw < 6);

    // Weight cosines for positions p = 4k..4k+3 (q = p mod 10), computed once.
    float cw0, cw1, cw2, cw3;
    {
        int p = 4 * k;
        int q0 = (p     < NQ) ? p     : p - NQ;
        int q1 = (p + 1 < NQ) ? p + 1 : p + 1 - NQ;
        int q2 = (p + 2 < NQ) ? p + 2 : p + 2 - NQ;
        int q3 = (p + 3 < NQ) ? p + 3 : p + 3 - NQ;
        cw0 = __cosf(__ldg(&w[q0]));
        cw1 = __cosf(__ldg(&w[q1]));
        cw2 = __cosf(__ldg(&w[q2]));
        cw3 = __cosf(__ldg(&w[q3]));
    }

    bool r2 = (k == 2);                          // in-thread row boundary lane
    int srcA = base + ((k >= 3) ? 2 : 0);
    int srcB = base + ((k == 4) ? 3 : 1);

    int g0    = warp * (6 * ILP) + gw;           // first group of this lane
    int base4 = g0 * 5 + k;                      // its float4 index

    float4 a[ILP];
    // Front-batch ALL loads: MLP = ILP. Predicated, single path.
#pragma unroll
    for (int it = 0; it < ILP; it++) {
        bool act = lane_ok && (g0 + it * 6 < n_groups);
        a[it] = act ? __ldcs(&x4[base4 + it * 30])
                    : make_float4(0.f, 0.f, 0.f, 0.f);
    }

#pragma unroll
    for (int it = 0; it < ILP; it++) {
        float c0 = __cosf(a[it].x) * cw0;
        float c1 = __cosf(a[it].y) * cw1;
        float c2 = __cosf(a[it].z) * cw2;
        float c3 = __cosf(a[it].w) * cw3;

        // Local segmented inclusive scan (reset at p=10 -> k==2, j==2)
        float lp0 = c0;
        float lp1 = lp0 * c1;
        float lp2 = r2 ? c2 : lp1 * c2;
        float lp3 = lp2 * c3;

        // Cross-lane exclusive prefix (2 IDX shuffles)
        float sA = __shfl_sync(0xffffffffu, lp3, srcA);
        float sB = __shfl_sync(0xffffffffu, lp3, srcB);
        float pre = (k == 0) ? 1.0f
                  : (k == 1 || k == 3) ? sA
                  : sA * sB;
        float pre_hi = r2 ? 1.0f : pre;

        float4 r;
        r.x = lp0 * pre;
        r.y = lp1 * pre;
        r.z = lp2 * pre_hi;
        r.w = lp3 * pre_hi;

        bool act = lane_ok && (g0 + it * 6 < n_groups);
        if (act) __stcs(&o4[base4 + it * 30], r);
    }
}

extern "C" void kernel_launch(void* const* d_in, const int* in_sizes, int n_in,
                              void* d_out, int out_size)
{
    const float* x = (const float*)d_in[0];   // [16384*256*10] fp32
    const float* w = (const float*)d_in[1];   // [10] fp32
    float* out = (float*)d_out;

    long long total = (long long)in_sizes[0];   // 41,943,040 floats
    int n_groups    = (int)(total / 20);        // 2,097,152 groups of 20 floats
    long long warps = ((long long)n_groups + 6 * ILP - 1) / (6 * ILP);
    long long threads = warps * 32;
    int block = 256;
    long long grid = (threads + block - 1) / block;

    qattn_main<<<(unsigned)grid, block>>>(reinterpret_cast<const float4*>(x),
                                          reinterpret_cast<float4*>(out),
                                          w, n_groups);
}